// round 3
// baseline (speedup 1.0000x reference)
#include <cuda_runtime.h>
#include <math.h>

#define B_ 4
#define T_ 2048
#define C_ 1024
#define H_ 16
#define D_ 64
#define M_ (B_*T_)    // 8192
#define N3_ (3*C_)    // 3072

// Scratch (allocation-free rule: __device__ globals)
__device__ float g_Q[(size_t)B_*H_*T_*D_];
__device__ float g_K[(size_t)B_*H_*T_*D_];
__device__ float g_V[(size_t)B_*H_*T_*D_];
__device__ float g_attn[(size_t)M_*C_];

// ---------------------------------------------------------------------------
// Tiled SGEMM 128x128x8, 8x8 per thread, 256 threads.
// Mode SCATTER_QKV: write into g_Q/g_K/g_V in [b*H+h][t][d] layout.
// Mode !SCATTER_QKV: plain out[m*N + n] = acc + bias; A read from g_attn when
// A_FROM_GATTN.
// ---------------------------------------------------------------------------
template<int N, bool SCATTER_QKV, bool A_FROM_GATTN>
__global__ __launch_bounds__(256) void gemm_kernel(const float* __restrict__ A,
                                                   const float* __restrict__ Wm,
                                                   const float* __restrict__ bias,
                                                   float* __restrict__ out) {
    __shared__ float As[8][128];
    __shared__ float Bs[8][128];
    const int n0 = blockIdx.x * 128;
    const int m0 = blockIdx.y * 128;
    const int tid = threadIdx.x;
    const int tx = tid & 15, ty = tid >> 4;
    const int arow = tid >> 1, acol = (tid & 1) * 4;
    const int brow = tid >> 5, bcol = (tid & 31) * 4;

    const float* Ap = A_FROM_GATTN ? g_attn : A;

    float acc[8][8];
#pragma unroll
    for (int i = 0; i < 8; i++)
#pragma unroll
        for (int j = 0; j < 8; j++) acc[i][j] = 0.f;

    const float* Aptr = Ap + (size_t)(m0 + arow) * C_ + acol;
    const float* Bptr = Wm + (size_t)brow * N + n0 + bcol;

    for (int k0 = 0; k0 < C_; k0 += 8) {
        float4 a4 = *(const float4*)(Aptr + k0);
        As[acol + 0][arow] = a4.x;
        As[acol + 1][arow] = a4.y;
        As[acol + 2][arow] = a4.z;
        As[acol + 3][arow] = a4.w;
        float4 b4 = *(const float4*)(Bptr + (size_t)k0 * N);
        *(float4*)&Bs[brow][bcol] = b4;
        __syncthreads();
#pragma unroll
        for (int k = 0; k < 8; k++) {
            float ar[8], br[8];
#pragma unroll
            for (int i = 0; i < 8; i++) ar[i] = As[k][ty * 8 + i];
#pragma unroll
            for (int j = 0; j < 8; j++) br[j] = Bs[k][tx * 8 + j];
#pragma unroll
            for (int i = 0; i < 8; i++)
#pragma unroll
                for (int j = 0; j < 8; j++)
                    acc[i][j] = fmaf(ar[i], br[j], acc[i][j]);
        }
        __syncthreads();
    }

#pragma unroll
    for (int i = 0; i < 8; i++) {
        const int m = m0 + ty * 8 + i;
        const int b = m / T_, t = m % T_;
#pragma unroll
        for (int j = 0; j < 8; j++) {
            const int n = n0 + tx * 8 + j;
            const float v = acc[i][j] + bias[n];
            if (SCATTER_QKV) {
                const int which = n / C_;
                const int c = n % C_;
                const int h = c / D_, d = c % D_;
                float* dst = (which == 0) ? g_Q : (which == 1) ? g_K : g_V;
                dst[(((size_t)(b * H_ + h)) * T_ + t) * D_ + d] = v;
            } else {
                out[(size_t)m * N + n] = v;
            }
        }
    }
}

// ---------------------------------------------------------------------------
// Flash attention, causal. Br=Bc=64, D=64. 256 threads, 4x4 micro-tile per
// thread (16x16 thread grid). Online softmax with per-16-lane shuffle
// reductions (lanes of one row group are 16 consecutive lanes of a warp).
// ---------------------------------------------------------------------------
#define FLASH_SMEM_FLOATS (64*64 + 64*65 + 64*64 + 64*64)
#define FLASH_SMEM_BYTES  (FLASH_SMEM_FLOATS * 4)

__global__ __launch_bounds__(256) void flash_kernel() {
    extern __shared__ float sm[];
    float* Qs  = sm;                 // [64][64]
    float* KsT = Qs + 64 * 64;       // [64][65]  KsT[k][c] = K[c][k]
    float* Vs  = KsT + 64 * 65;      // [64][64]  Vs[k][c]
    float* Ps  = Vs + 64 * 64;       // [64][64]  P[r][k]

    const int bh = blockIdx.y;
    const int b = bh / H_, h = bh % H_;
    const int qt0 = blockIdx.x * 64;
    const int tid = threadIdx.x;
    const int tx = tid & 15, ty = tid >> 4;
    const int r0 = ty * 4, c0 = tx * 4;
    const float scale = 0.125f;  // D^-0.5

    const float* Qg = g_Q + (size_t)bh * T_ * D_;
    const float* Kg = g_K + (size_t)bh * T_ * D_;
    const float* Vg = g_V + (size_t)bh * T_ * D_;

    for (int idx = tid; idx < 64 * 64; idx += 256)
        Qs[idx] = Qg[(size_t)qt0 * 64 + idx];

    float o[4][4];
    float mrow[4], lrow[4];
#pragma unroll
    for (int i = 0; i < 4; i++) {
        mrow[i] = -1e30f;
        lrow[i] = 0.f;
#pragma unroll
        for (int j = 0; j < 4; j++) o[i][j] = 0.f;
    }
    __syncthreads();

    for (int kv0 = 0; kv0 <= qt0; kv0 += 64) {
        // Load K^T (padded stride 65) and V
        for (int idx = tid; idx < 64 * 64; idx += 256) {
            const int cc = idx >> 6, kk = idx & 63;
            KsT[kk * 65 + cc] = Kg[(size_t)(kv0 + cc) * 64 + kk];
            Vs[idx] = Vg[(size_t)kv0 * 64 + idx];
        }
        __syncthreads();

        // S = scale * Q K^T
        float s[4][4];
#pragma unroll
        for (int i = 0; i < 4; i++)
#pragma unroll
            for (int j = 0; j < 4; j++) s[i][j] = 0.f;

        for (int k = 0; k < 64; k++) {
            float qv[4], kv[4];
#pragma unroll
            for (int i = 0; i < 4; i++) qv[i] = Qs[(r0 + i) * 64 + k];
#pragma unroll
            for (int j = 0; j < 4; j++) kv[j] = KsT[k * 65 + c0 + j];
#pragma unroll
            for (int i = 0; i < 4; i++)
#pragma unroll
                for (int j = 0; j < 4; j++)
                    s[i][j] = fmaf(qv[i], kv[j], s[i][j]);
        }
#pragma unroll
        for (int i = 0; i < 4; i++)
#pragma unroll
            for (int j = 0; j < 4; j++) s[i][j] *= scale;

        if (kv0 == qt0) {  // only diagonal tile needs masking
#pragma unroll
            for (int i = 0; i < 4; i++)
#pragma unroll
                for (int j = 0; j < 4; j++)
                    if (c0 + j > r0 + i) s[i][j] = -1e30f;
        }

        // Online softmax per row (16 lanes per row group, consecutive lanes)
#pragma unroll
        for (int i = 0; i < 4; i++) {
            float tm = fmaxf(fmaxf(s[i][0], s[i][1]), fmaxf(s[i][2], s[i][3]));
#pragma unroll
            for (int off = 1; off < 16; off <<= 1)
                tm = fmaxf(tm, __shfl_xor_sync(0xffffffffu, tm, off));
            const float newm = fmaxf(mrow[i], tm);
            float p[4], ls = 0.f;
#pragma unroll
            for (int j = 0; j < 4; j++) {
                p[j] = __expf(s[i][j] - newm);
                ls += p[j];
            }
#pragma unroll
            for (int off = 1; off < 16; off <<= 1)
                ls += __shfl_xor_sync(0xffffffffu, ls, off);
            const float alpha = __expf(mrow[i] - newm);
            lrow[i] = lrow[i] * alpha + ls;
            mrow[i] = newm;
#pragma unroll
            for (int j = 0; j < 4; j++) o[i][j] *= alpha;
#pragma unroll
            for (int j = 0; j < 4; j++) Ps[(r0 + i) * 64 + c0 + j] = p[j];
        }
        __syncthreads();

        // O += P @ V
        for (int k = 0; k < 64; k++) {
            const float4 vv = *(const float4*)&Vs[k * 64 + c0];
            float pv[4];
#pragma unroll
            for (int i = 0; i < 4; i++) pv[i] = Ps[(r0 + i) * 64 + k];
#pragma unroll
            for (int i = 0; i < 4; i++) {
                o[i][0] = fmaf(pv[i], vv.x, o[i][0]);
                o[i][1] = fmaf(pv[i], vv.y, o[i][1]);
                o[i][2] = fmaf(pv[i], vv.z, o[i][2]);
                o[i][3] = fmaf(pv[i], vv.w, o[i][3]);
            }
        }
        __syncthreads();
    }

    // Normalize and write to g_attn in [B, T, C] layout (row m = b*T+t, col h*D+d)
#pragma unroll
    for (int i = 0; i < 4; i++) {
        const float inv = 1.0f / lrow[i];
        const int t = qt0 + r0 + i;
        float4 res;
        res.x = o[i][0] * inv;
        res.y = o[i][1] * inv;
        res.z = o[i][2] * inv;
        res.w = o[i][3] * inv;
        *(float4*)&g_attn[((size_t)(b * T_ + t)) * C_ + h * D_ + c0] = res;
    }
}

// ---------------------------------------------------------------------------
extern "C" void kernel_launch(void* const* d_in, const int* in_sizes, int n_in,
                              void* d_out, int out_size) {
    const float* x      = (const float*)d_in[0];
    const float* w_qkv  = (const float*)d_in[1];
    const float* b_qkv  = (const float*)d_in[2];
    const float* w_proj = (const float*)d_in[3];
    const float* b_proj = (const float*)d_in[4];
    float* out = (float*)d_out;

    cudaFuncSetAttribute(flash_kernel,
                         cudaFuncAttributeMaxDynamicSharedMemorySize,
                         FLASH_SMEM_BYTES);

    // 1) QKV GEMM + scatter to [bh][t][d]
    dim3 gq(N3_ / 128, M_ / 128);  // (24, 64)
    gemm_kernel<N3_, true, false><<<gq, 256>>>(x, w_qkv, b_qkv, nullptr);

    // 2) Causal flash attention -> g_attn [B,T,C]
    dim3 gf(T_ / 64, B_ * H_);     // (32, 64)
    flash_kernel<<<gf, 256, FLASH_SMEM_BYTES>>>();

    // 3) Output projection
    dim3 gp(C_ / 128, M_ / 128);   // (8, 64)
    gemm_kernel<C_, false, true><<<gp, 256>>>(nullptr, w_proj, b_proj, out);
}

// round 6
// speedup vs baseline: 2.3853x; 2.3853x over previous
#include <cuda_runtime.h>
#include <cuda_bf16.h>
#include <math.h>
#include <stdint.h>

#define B_ 4
#define T_ 2048
#define C_ 1024
#define H_ 16
#define D_ 64
#define M_ (B_*T_)    // 8192
#define N3_ (3*C_)    // 3072
#define BH_ (B_*H_)   // 64

// ---------------------------------------------------------------------------
// Scratch (__device__ globals: allocation-free rule)
// ---------------------------------------------------------------------------
__device__ float g_Q[(size_t)BH_*T_*D_];
__device__ float g_K[(size_t)BH_*T_*D_];
__device__ float g_V[(size_t)BH_*T_*D_];
__device__ float g_attn[(size_t)M_*C_];

__device__ __nv_bfloat16 g_Xhi[(size_t)M_*C_];
__device__ __nv_bfloat16 g_Xlo[(size_t)M_*C_];
__device__ __nv_bfloat16 g_A2hi[(size_t)M_*C_];
__device__ __nv_bfloat16 g_A2lo[(size_t)M_*C_];
__device__ __nv_bfloat16 g_WqkvT_hi[(size_t)N3_*C_];
__device__ __nv_bfloat16 g_WqkvT_lo[(size_t)N3_*C_];
__device__ __nv_bfloat16 g_WprojT_hi[(size_t)C_*C_];
__device__ __nv_bfloat16 g_WprojT_lo[(size_t)C_*C_];

__device__ __nv_bfloat16 g_Qhi[(size_t)BH_*T_*D_];   // [bh][t][d], pre-scaled by D^-0.5
__device__ __nv_bfloat16 g_Qlo[(size_t)BH_*T_*D_];
__device__ __nv_bfloat16 g_Khi[(size_t)BH_*T_*D_];   // [bh][t][d]
__device__ __nv_bfloat16 g_Klo[(size_t)BH_*T_*D_];
__device__ __nv_bfloat16 g_Vthi[(size_t)BH_*D_*T_];  // [bh][d][t]  (transposed)
__device__ __nv_bfloat16 g_Vtlo[(size_t)BH_*D_*T_];

// ---------------------------------------------------------------------------
// mma.sync / ldmatrix helpers (portable sm_80+ PTX: compiles for sm_103)
// ---------------------------------------------------------------------------
__device__ __forceinline__ uint32_t smem_to_u32(const void* p) {
    uint32_t a;
    asm("{ .reg .u64 t; cvta.to.shared.u64 t, %1; cvt.u32.u64 %0, t; }"
        : "=r"(a) : "l"(p));
    return a;
}

__device__ __forceinline__ void ldsm4(uint32_t* r, uint32_t addr) {
    asm volatile("ldmatrix.sync.aligned.m8n8.x4.shared.b16 {%0,%1,%2,%3}, [%4];"
                 : "=r"(r[0]), "=r"(r[1]), "=r"(r[2]), "=r"(r[3]) : "r"(addr));
}

__device__ __forceinline__ void mma16816(float* c, const uint32_t* a,
                                         uint32_t b0, uint32_t b1) {
    asm volatile(
        "mma.sync.aligned.m16n8k16.row.col.f32.bf16.bf16.f32 "
        "{%0,%1,%2,%3}, {%4,%5,%6,%7}, {%8,%9}, {%0,%1,%2,%3};"
        : "+f"(c[0]), "+f"(c[1]), "+f"(c[2]), "+f"(c[3])
        : "r"(a[0]), "r"(a[1]), "r"(a[2]), "r"(a[3]), "r"(b0), "r"(b1));
}

// Swizzled smem tile: [rows][64 bf16] = 128B rows, 16B chunks XOR-swizzled.
__device__ __forceinline__ uint32_t lda_sw(int r, int c) {
    return (uint32_t)((r << 7) | (((c ^ (r & 7)) & 7) << 4));
}

__device__ __forceinline__ uint32_t pack_bf16(float lo_, float hi_) {
    __nv_bfloat162 t = __floats2bfloat162_rn(lo_, hi_);  // x=lo_, y=hi_
    return *(uint32_t*)&t;
}

// ---------------------------------------------------------------------------
// Conversion kernels
// ---------------------------------------------------------------------------
template<int SRC_ATTN>   // 0: x -> g_X*, 1: g_attn -> g_A2*
__global__ void convert_split(const float* __restrict__ in) {
    const float* src = SRC_ATTN ? g_attn : in;
    __nv_bfloat16* hi = SRC_ATTN ? g_A2hi : g_Xhi;
    __nv_bfloat16* lo = SRC_ATTN ? g_A2lo : g_Xlo;
    size_t i = (size_t)blockIdx.x * blockDim.x + threadIdx.x;
    float4 v = ((const float4*)src)[i];
    float f[4] = {v.x, v.y, v.z, v.w};
    __nv_bfloat16 h[4], l[4];
#pragma unroll
    for (int k = 0; k < 4; k++) {
        h[k] = __float2bfloat16_rn(f[k]);
        l[k] = __float2bfloat16_rn(f[k] - __bfloat162float(h[k]));
    }
    ((__nv_bfloat162*)(hi + i * 4))[0] = __nv_bfloat162(h[0], h[1]);
    ((__nv_bfloat162*)(hi + i * 4))[1] = __nv_bfloat162(h[2], h[3]);
    ((__nv_bfloat162*)(lo + i * 4))[0] = __nv_bfloat162(l[0], l[1]);
    ((__nv_bfloat162*)(lo + i * 4))[1] = __nv_bfloat162(l[2], l[3]);
}

// W [K][N] fp32 -> Wt hi/lo [N][K] bf16 (transpose + split)
template<int WHICH>
__global__ void transpose_split(const float* __restrict__ W, int Kdim, int Ndim) {
    __nv_bfloat16* Thi = WHICH ? g_WprojT_hi : g_WqkvT_hi;
    __nv_bfloat16* Tlo = WHICH ? g_WprojT_lo : g_WqkvT_lo;
    __shared__ float tile[32][33];
    int x = blockIdx.x * 32 + threadIdx.x;
    int y0 = blockIdx.y * 32;
#pragma unroll
    for (int j = 0; j < 32; j += 8)
        tile[threadIdx.y + j][threadIdx.x] = W[(size_t)(y0 + threadIdx.y + j) * Ndim + x];
    __syncthreads();
    int xo = y0 + threadIdx.x;
    int yo0 = blockIdx.x * 32;
#pragma unroll
    for (int j = 0; j < 32; j += 8) {
        float v = tile[threadIdx.x][threadIdx.y + j];
        __nv_bfloat16 h = __float2bfloat16_rn(v);
        __nv_bfloat16 l = __float2bfloat16_rn(v - __bfloat162float(h));
        size_t o = (size_t)(yo0 + threadIdx.y + j) * Kdim + xo;
        Thi[o] = h; Tlo[o] = l;
    }
}

// Q (scaled by D^-0.5) and K -> bf16 hi/lo, same [bh][t][d] layout
__global__ void conv_qk() {
    size_t i = (size_t)blockIdx.x * blockDim.x + threadIdx.x;  // vec4 index
    float4 q = ((const float4*)g_Q)[i];
    float4 k = ((const float4*)g_K)[i];
    float fq[4] = {q.x * 0.125f, q.y * 0.125f, q.z * 0.125f, q.w * 0.125f};
    float fk[4] = {k.x, k.y, k.z, k.w};
    __nv_bfloat16 qh[4], ql[4], kh[4], kl[4];
#pragma unroll
    for (int j = 0; j < 4; j++) {
        qh[j] = __float2bfloat16_rn(fq[j]);
        ql[j] = __float2bfloat16_rn(fq[j] - __bfloat162float(qh[j]));
        kh[j] = __float2bfloat16_rn(fk[j]);
        kl[j] = __float2bfloat16_rn(fk[j] - __bfloat162float(kh[j]));
    }
    ((__nv_bfloat162*)(g_Qhi + i * 4))[0] = __nv_bfloat162(qh[0], qh[1]);
    ((__nv_bfloat162*)(g_Qhi + i * 4))[1] = __nv_bfloat162(qh[2], qh[3]);
    ((__nv_bfloat162*)(g_Qlo + i * 4))[0] = __nv_bfloat162(ql[0], ql[1]);
    ((__nv_bfloat162*)(g_Qlo + i * 4))[1] = __nv_bfloat162(ql[2], ql[3]);
    ((__nv_bfloat162*)(g_Khi + i * 4))[0] = __nv_bfloat162(kh[0], kh[1]);
    ((__nv_bfloat162*)(g_Khi + i * 4))[1] = __nv_bfloat162(kh[2], kh[3]);
    ((__nv_bfloat162*)(g_Klo + i * 4))[0] = __nv_bfloat162(kl[0], kl[1]);
    ((__nv_bfloat162*)(g_Klo + i * 4))[1] = __nv_bfloat162(kl[2], kl[3]);
}

// V [bh][t][d] fp32 -> Vt hi/lo [bh][d][t] bf16
__global__ void vtrans() {
    __shared__ float tile[32][33];
    int bh = blockIdx.z;
    const float* src = g_V + (size_t)bh * T_ * D_;
    int t0 = blockIdx.x * 32, d0 = blockIdx.y * 32;
#pragma unroll
    for (int j = 0; j < 32; j += 8)
        tile[threadIdx.y + j][threadIdx.x] = src[(size_t)(t0 + threadIdx.y + j) * D_ + d0 + threadIdx.x];
    __syncthreads();
#pragma unroll
    for (int j = 0; j < 32; j += 8) {
        float v = tile[threadIdx.x][threadIdx.y + j];
        __nv_bfloat16 h = __float2bfloat16_rn(v);
        __nv_bfloat16 l = __float2bfloat16_rn(v - __bfloat162float(h));
        size_t o = ((size_t)bh * D_ + d0 + threadIdx.y + j) * T_ + t0 + threadIdx.x;
        g_Vthi[o] = h; g_Vtlo[o] = l;
    }
}

// ---------------------------------------------------------------------------
// HMMA GEMM: 128x128 CTA tile, 8 warps (warp tile 64x32), k-chunk 64.
// acc += Ahi*Bhi + Ahi*Blo + Alo*Bhi (fp32 acc). B stored [N][K] K-major.
// CFG 0: A=g_X*, B=g_WqkvT_* -> scatter Q/K/V fp32. CFG 1: A=g_A2*, B=g_WprojT_* -> out.
// ---------------------------------------------------------------------------
#define GEMM_SMEM (4*16384)   // Ahi, Alo, Bhi, Blo tiles [128][64]bf16

template<int CFG>
__global__ __launch_bounds__(256) void gemm_mma(const float* __restrict__ bias,
                                               float* __restrict__ out) {
    extern __shared__ __align__(128) char gsm[];
    const __nv_bfloat16* Ah = CFG ? g_A2hi : g_Xhi;
    const __nv_bfloat16* Al = CFG ? g_A2lo : g_Xlo;
    const __nv_bfloat16* Bh = CFG ? g_WprojT_hi : g_WqkvT_hi;
    const __nv_bfloat16* Bl = CFG ? g_WprojT_lo : g_WqkvT_lo;

    const uint32_t sb = smem_to_u32(gsm);
    const uint32_t sAh = sb, sAl = sb + 16384, sBh = sb + 32768, sBl = sb + 49152;
    const int tid = threadIdx.x, lane = tid & 31, w = tid >> 5;
    const int wr = w >> 2, wc = w & 3;             // warp grid 2x4
    const int n0 = blockIdx.x * 128, m0 = blockIdx.y * 128;

    float acc[4][4][4];
#pragma unroll
    for (int a = 0; a < 4; a++)
#pragma unroll
        for (int b = 0; b < 4; b++)
#pragma unroll
            for (int c = 0; c < 4; c++) acc[a][b][c] = 0.f;

    const int fr = lane & 15, fc = lane >> 4;      // ldmatrix address pattern

    for (int c16 = 0; c16 < C_ / 64; c16++) {
        const int k0 = c16 * 64;
        if (c16) __syncthreads();
#pragma unroll
        for (int i = 0; i < 4; i++) {
            const int id = i * 256 + tid;
            const int r = id >> 3, ch = id & 7;
            const uint32_t so = lda_sw(r, ch);
            const size_t ga = (size_t)(m0 + r) * C_ + k0 + ch * 8;
            const size_t gb = (size_t)(n0 + r) * C_ + k0 + ch * 8;
            *(uint4*)(gsm + so)         = *(const uint4*)(Ah + ga);
            *(uint4*)(gsm + 16384 + so) = *(const uint4*)(Al + ga);
            *(uint4*)(gsm + 32768 + so) = *(const uint4*)(Bh + gb);
            *(uint4*)(gsm + 49152 + so) = *(const uint4*)(Bl + gb);
        }
        __syncthreads();

#pragma unroll
        for (int ks = 0; ks < 4; ks++) {
            uint32_t a_h[4][4], a_l[4][4];
#pragma unroll
            for (int mt = 0; mt < 4; mt++) {
                const uint32_t off = lda_sw(wr * 64 + mt * 16 + fr, 2 * ks + fc);
                ldsm4(a_h[mt], sAh + off);
                ldsm4(a_l[mt], sAl + off);
            }
#pragma unroll
            for (int nt2 = 0; nt2 < 2; nt2++) {
                uint32_t b_h[4], b_l[4];
                const uint32_t off = lda_sw(wc * 32 + nt2 * 16 + fr, 2 * ks + fc);
                ldsm4(b_h, sBh + off);
                ldsm4(b_l, sBl + off);
#pragma unroll
                for (int mt = 0; mt < 4; mt++) {
                    mma16816(acc[mt][nt2 * 2],     a_h[mt], b_h[0], b_h[2]);
                    mma16816(acc[mt][nt2 * 2 + 1], a_h[mt], b_h[1], b_h[3]);
                    mma16816(acc[mt][nt2 * 2],     a_h[mt], b_l[0], b_l[2]);
                    mma16816(acc[mt][nt2 * 2 + 1], a_h[mt], b_l[1], b_l[3]);
                    mma16816(acc[mt][nt2 * 2],     a_l[mt], b_h[0], b_h[2]);
                    mma16816(acc[mt][nt2 * 2 + 1], a_l[mt], b_h[1], b_h[3]);
                }
            }
        }
    }

    // Epilogue. C-fragment: c0,c1 -> (row grp, col q,q+1); c2,c3 -> row grp+8.
    const int grp = lane >> 2, qc = (lane & 3) * 2;
#pragma unroll
    for (int mt = 0; mt < 4; mt++) {
        const int m1 = m0 + wr * 64 + mt * 16 + grp;
        const int m2 = m1 + 8;
        const int b1 = m1 / T_, t1 = m1 % T_;
        const int b2 = m2 / T_, t2 = m2 % T_;
#pragma unroll
        for (int nt = 0; nt < 4; nt++) {
            const int n = n0 + wc * 32 + nt * 8 + qc;
            const float bs0 = bias[n], bs1 = bias[n + 1];
            float2 vA = make_float2(acc[mt][nt][0] + bs0, acc[mt][nt][1] + bs1);
            float2 vB = make_float2(acc[mt][nt][2] + bs0, acc[mt][nt][3] + bs1);
            if (CFG == 0) {
                const int which = n / C_, ci = n % C_;
                const int h = ci / D_, d = ci % D_;
                float* dst = (which == 0) ? g_Q : (which == 1) ? g_K : g_V;
                *(float2*)(dst + (((size_t)(b1 * H_ + h)) * T_ + t1) * D_ + d) = vA;
                *(float2*)(dst + (((size_t)(b2 * H_ + h)) * T_ + t2) * D_ + d) = vB;
            } else {
                *(float2*)(out + (size_t)m1 * C_ + n) = vA;
                *(float2*)(out + (size_t)m2 * C_ + n) = vB;
            }
        }
    }
}

// ---------------------------------------------------------------------------
// HMMA flash attention, causal. Br=64, Bc=64, D=64, 4 warps (128 thr).
// S = (Qhi+Qlo)(Khi+Klo)^T (3 terms, scale folded into Q); online softmax on
// fragments; P hi/lo split in registers; O += P * Vt (3 terms).
// ---------------------------------------------------------------------------
#define FL_SMEM (6*8192)   // Qhi,Qlo,Khi,Klo,Vthi,Vtlo tiles [64][64]bf16

__global__ __launch_bounds__(128) void flash_mma() {
    extern __shared__ __align__(128) char fsm[];
    const uint32_t sb = smem_to_u32(fsm);
    const uint32_t sQh = sb, sQl = sb + 8192, sKh = sb + 16384, sKl = sb + 24576,
                   sVh = sb + 32768, sVl = sb + 40960;
    const int tid = threadIdx.x, lane = tid & 31, w = tid >> 5;
    const int bh = blockIdx.y, b = bh >> 4, h = bh & 15;
    const int qt0 = blockIdx.x * 64;
    const int fr = lane & 15, fc = lane >> 4;
    const int grp = lane >> 2, qc = (lane & 3) * 2;

    const size_t bhoff = (size_t)bh * T_ * D_;

    // Load Q tiles (rows qt0..qt0+63)
#pragma unroll
    for (int i = 0; i < 4; i++) {
        const int id = i * 128 + tid;
        const int r = id >> 3, ch = id & 7;
        const uint32_t so = lda_sw(r, ch);
        const size_t g = bhoff + (size_t)(qt0 + r) * D_ + ch * 8;
        *(uint4*)(fsm + so)        = *(const uint4*)(g_Qhi + g);
        *(uint4*)(fsm + 8192 + so) = *(const uint4*)(g_Qlo + g);
    }
    __syncthreads();

    // Preload Q fragments (warp rows w*16..+16)
    uint32_t qh[4][4], ql[4][4];
#pragma unroll
    for (int ks = 0; ks < 4; ks++) {
        const uint32_t off = lda_sw(w * 16 + fr, 2 * ks + fc);
        ldsm4(qh[ks], sQh + off);
        ldsm4(ql[ks], sQl + off);
    }

    float o[8][4];
#pragma unroll
    for (int d = 0; d < 8; d++)
#pragma unroll
        for (int r = 0; r < 4; r++) o[d][r] = 0.f;
    float mA = -1e30f, mB = -1e30f, lA = 0.f, lB = 0.f;

    const int rowA = qt0 + w * 16 + grp;     // global q row for c0,c1
    const int rowB = rowA + 8;               // for c2,c3

    for (int kv0 = 0; kv0 <= qt0; kv0 += 64) {
        __syncthreads();
#pragma unroll
        for (int i = 0; i < 4; i++) {
            const int id = i * 128 + tid;
            const int r = id >> 3, ch = id & 7;
            const uint32_t so = lda_sw(r, ch);
            const size_t gk = bhoff + (size_t)(kv0 + r) * D_ + ch * 8;
            const size_t gv = (size_t)bh * D_ * T_ + (size_t)r * T_ + kv0 + ch * 8;
            *(uint4*)(fsm + 16384 + so) = *(const uint4*)(g_Khi + gk);
            *(uint4*)(fsm + 24576 + so) = *(const uint4*)(g_Klo + gk);
            *(uint4*)(fsm + 32768 + so) = *(const uint4*)(g_Vthi + gv);
            *(uint4*)(fsm + 40960 + so) = *(const uint4*)(g_Vtlo + gv);
        }
        __syncthreads();

        // S = Q K^T (scaled; 3 terms)
        float s[8][4];
#pragma unroll
        for (int nt = 0; nt < 8; nt++)
#pragma unroll
            for (int r = 0; r < 4; r++) s[nt][r] = 0.f;

#pragma unroll
        for (int ks = 0; ks < 4; ks++) {
#pragma unroll
            for (int nt2 = 0; nt2 < 4; nt2++) {
                uint32_t bhr[4], blr[4];
                const uint32_t off = lda_sw(nt2 * 16 + fr, 2 * ks + fc);
                ldsm4(bhr, sKh + off);
                ldsm4(blr, sKl + off);
                mma16816(s[nt2 * 2],     qh[ks], bhr[0], bhr[2]);
                mma16816(s[nt2 * 2 + 1], qh[ks], bhr[1], bhr[3]);
                mma16816(s[nt2 * 2],     qh[ks], blr[0], blr[2]);
                mma16816(s[nt2 * 2 + 1], qh[ks], blr[1], blr[3]);
                mma16816(s[nt2 * 2],     ql[ks], bhr[0], bhr[2]);
                mma16816(s[nt2 * 2 + 1], ql[ks], bhr[1], bhr[3]);
            }
        }

        if (kv0 == qt0) {   // diagonal tile: causal mask
#pragma unroll
            for (int nt = 0; nt < 8; nt++) {
                const int cb = kv0 + nt * 8 + qc;
                if (cb > rowA)     s[nt][0] = -1e30f;
                if (cb + 1 > rowA) s[nt][1] = -1e30f;
                if (cb > rowB)     s[nt][2] = -1e30f;
                if (cb + 1 > rowB) s[nt][3] = -1e30f;
            }
        }

        // Online softmax (rows rowA / rowB owned by lane%4 groups)
        float mxA = -1e30f, mxB = -1e30f;
#pragma unroll
        for (int nt = 0; nt < 8; nt++) {
            mxA = fmaxf(mxA, fmaxf(s[nt][0], s[nt][1]));
            mxB = fmaxf(mxB, fmaxf(s[nt][2], s[nt][3]));
        }
        mxA = fmaxf(mxA, __shfl_xor_sync(0xffffffffu, mxA, 1));
        mxA = fmaxf(mxA, __shfl_xor_sync(0xffffffffu, mxA, 2));
        mxB = fmaxf(mxB, __shfl_xor_sync(0xffffffffu, mxB, 1));
        mxB = fmaxf(mxB, __shfl_xor_sync(0xffffffffu, mxB, 2));
        const float nmA = fmaxf(mA, mxA), nmB = fmaxf(mB, mxB);
        const float aA = __expf(mA - nmA), aB = __expf(mB - nmB);

        float p[8][4];
        float sumA = 0.f, sumB = 0.f;
#pragma unroll
        for (int nt = 0; nt < 8; nt++) {
            p[nt][0] = __expf(s[nt][0] - nmA);
            p[nt][1] = __expf(s[nt][1] - nmA);
            p[nt][2] = __expf(s[nt][2] - nmB);
            p[nt][3] = __expf(s[nt][3] - nmB);
            sumA += p[nt][0] + p[nt][1];
            sumB += p[nt][2] + p[nt][3];
        }
        sumA += __shfl_xor_sync(0xffffffffu, sumA, 1);
        sumA += __shfl_xor_sync(0xffffffffu, sumA, 2);
        sumB += __shfl_xor_sync(0xffffffffu, sumB, 1);
        sumB += __shfl_xor_sync(0xffffffffu, sumB, 2);
        lA = lA * aA + sumA;
        lB = lB * aB + sumB;
        mA = nmA; mB = nmB;
#pragma unroll
        for (int d = 0; d < 8; d++) {
            o[d][0] *= aA; o[d][1] *= aA;
            o[d][2] *= aB; o[d][3] *= aB;
        }

        // O += P * Vt (P hi/lo split in registers)
#pragma unroll
        for (int ks = 0; ks < 4; ks++) {
            // A-fragment of P for kv-cols [16ks,16ks+16): tiles 2ks, 2ks+1
            float f0 = p[2 * ks][0], f1 = p[2 * ks][1];
            float f2 = p[2 * ks][2], f3 = p[2 * ks][3];
            float f4 = p[2 * ks + 1][0], f5 = p[2 * ks + 1][1];
            float f6 = p[2 * ks + 1][2], f7 = p[2 * ks + 1][3];
            float h0 = __bfloat162float(__float2bfloat16_rn(f0));
            float h1 = __bfloat162float(__float2bfloat16_rn(f1));
            float h2 = __bfloat162float(__float2bfloat16_rn(f2));
            float h3 = __bfloat162float(__float2bfloat16_rn(f3));
            float h4 = __bfloat162float(__float2bfloat16_rn(f4));
            float h5 = __bfloat162float(__float2bfloat16_rn(f5));
            float h6 = __bfloat162float(__float2bfloat16_rn(f6));
            float h7 = __bfloat162float(__float2bfloat16_rn(f7));
            uint32_t pa_h[4], pa_l[4];
            pa_h[0] = pack_bf16(h0, h1); pa_h[1] = pack_bf16(h2, h3);
            pa_h[2] = pack_bf16(h4, h5); pa_h[3] = pack_bf16(h6, h7);
            pa_l[0] = pack_bf16(f0 - h0, f1 - h1);
            pa_l[1] = pack_bf16(f2 - h2, f3 - h3);
            pa_l[2] = pack_bf16(f4 - h4, f5 - h5);
            pa_l[3] = pack_bf16(f6 - h6, f7 - h7);
#pragma unroll
            for (int dt2 = 0; dt2 < 4; dt2++) {
                uint32_t vh4[4], vl4[4];
                const uint32_t off = lda_sw(dt2 * 16 + fr, 2 * ks + fc);
                ldsm4(vh4, sVh + off);
                ldsm4(vl4, sVl + off);
                mma16816(o[dt2 * 2],     pa_h, vh4[0], vh4[2]);
                mma16816(o[dt2 * 2 + 1], pa_h, vh4[1], vh4[3]);
                mma16816(o[dt2 * 2],     pa_h, vl4[0], vl4[2]);
                mma16816(o[dt2 * 2 + 1], pa_h, vl4[1], vl4[3]);
                mma16816(o[dt2 * 2],     pa_l, vh4[0], vh4[2]);
                mma16816(o[dt2 * 2 + 1], pa_l, vh4[1], vh4[3]);
            }
        }
    }

    // Normalize and write fp32 to g_attn [B,T,C]
    const float invA = 1.0f / lA, invB = 1.0f / lB;
#pragma unroll
    for (int dt = 0; dt < 8; dt++) {
        const int d = dt * 8 + qc;
        *(float2*)(g_attn + ((size_t)(b * T_ + rowA)) * C_ + h * D_ + d) =
            make_float2(o[dt][0] * invA, o[dt][1] * invA);
        *(float2*)(g_attn + ((size_t)(b * T_ + rowB)) * C_ + h * D_ + d) =
            make_float2(o[dt][2] * invB, o[dt][3] * invB);
    }
}

// ---------------------------------------------------------------------------
extern "C" void kernel_launch(void* const* d_in, const int* in_sizes, int n_in,
                              void* d_out, int out_size) {
    const float* x      = (const float*)d_in[0];
    const float* w_qkv  = (const float*)d_in[1];
    const float* b_qkv  = (const float*)d_in[2];
    const float* w_proj = (const float*)d_in[3];
    const float* b_proj = (const float*)d_in[4];
    float* out = (float*)d_out;

    cudaFuncSetAttribute(gemm_mma<0>, cudaFuncAttributeMaxDynamicSharedMemorySize, GEMM_SMEM);
    cudaFuncSetAttribute(gemm_mma<1>, cudaFuncAttributeMaxDynamicSharedMemorySize, GEMM_SMEM);
    cudaFuncSetAttribute(flash_mma,   cudaFuncAttributeMaxDynamicSharedMemorySize, FL_SMEM);

    // 0) input conversions
    convert_split<0><<<(M_ * C_ / 4) / 256, 256>>>(x);
    transpose_split<0><<<dim3(N3_ / 32, C_ / 32), dim3(32, 8)>>>(w_qkv, C_, N3_);
    transpose_split<1><<<dim3(C_ / 32, C_ / 32), dim3(32, 8)>>>(w_proj, C_, C_);

    // 1) QKV GEMM (HMMA, bf16 split) -> fp32 Q/K/V [bh][t][d]
    gemm_mma<0><<<dim3(N3_ / 128, M_ / 128), 256, GEMM_SMEM>>>(b_qkv, nullptr);

    // 2) Q/K -> bf16 hi/lo (Q pre-scaled), V -> transposed bf16 hi/lo
    conv_qk<<<((size_t)BH_ * T_ * D_ / 4) / 256, 256>>>();
    vtrans<<<dim3(T_ / 32, D_ / 32, BH_), dim3(32, 8)>>>();

    // 3) Causal flash attention (HMMA) -> g_attn [B,T,C] fp32
    flash_mma<<<dim3(T_ / 64, BH_), 128, FL_SMEM>>>();

    // 4) Output projection (HMMA, bf16 split)
    convert_split<1><<<(M_ * C_ / 4) / 256, 256>>>(nullptr);
    gemm_mma<1><<<dim3(C_ / 128, M_ / 128), 256, GEMM_SMEM>>>(b_proj, out);
}

// round 8
// speedup vs baseline: 3.1298x; 1.3122x over previous
#include <cuda_runtime.h>
#include <cuda_bf16.h>
#include <math.h>
#include <stdint.h>

#define B_ 4
#define T_ 2048
#define C_ 1024
#define H_ 16
#define D_ 64
#define M_ (B_*T_)    // 8192
#define N3_ (3*C_)    // 3072
#define BH_ (B_*H_)   // 64

// ---------------------------------------------------------------------------
// Scratch (__device__ globals: allocation-free rule)
// ---------------------------------------------------------------------------
__device__ __nv_bfloat16 g_Xhi[(size_t)M_*C_];
__device__ __nv_bfloat16 g_Xlo[(size_t)M_*C_];
__device__ __nv_bfloat16 g_A2hi[(size_t)M_*C_];
__device__ __nv_bfloat16 g_A2lo[(size_t)M_*C_];
__device__ __nv_bfloat16 g_WqkvT_hi[(size_t)N3_*C_];
__device__ __nv_bfloat16 g_WqkvT_lo[(size_t)N3_*C_];
__device__ __nv_bfloat16 g_WprojT_hi[(size_t)C_*C_];
__device__ __nv_bfloat16 g_WprojT_lo[(size_t)C_*C_];

__device__ __nv_bfloat16 g_Qhi[(size_t)BH_*T_*D_];   // [bh][t][d], pre-scaled D^-0.5
__device__ __nv_bfloat16 g_Qlo[(size_t)BH_*T_*D_];
__device__ __nv_bfloat16 g_Khi[(size_t)BH_*T_*D_];
__device__ __nv_bfloat16 g_Klo[(size_t)BH_*T_*D_];
__device__ __nv_bfloat16 g_Vthi[(size_t)BH_*D_*T_];  // [bh][d][t] (transposed)
__device__ __nv_bfloat16 g_Vtlo[(size_t)BH_*D_*T_];

// ---------------------------------------------------------------------------
// PTX helpers (portable sm_80+ path: compiles for vanilla sm_103)
// ---------------------------------------------------------------------------
__device__ __forceinline__ uint32_t smem_to_u32(const void* p) {
    uint32_t a;
    asm("{ .reg .u64 t; cvta.to.shared.u64 t, %1; cvt.u32.u64 %0, t; }"
        : "=r"(a) : "l"(p));
    return a;
}
__device__ __forceinline__ void ldsm4(uint32_t* r, uint32_t addr) {
    asm volatile("ldmatrix.sync.aligned.m8n8.x4.shared.b16 {%0,%1,%2,%3}, [%4];"
                 : "=r"(r[0]), "=r"(r[1]), "=r"(r[2]), "=r"(r[3]) : "r"(addr));
}
__device__ __forceinline__ void mma16816(float* c, const uint32_t* a,
                                         uint32_t b0, uint32_t b1) {
    asm volatile(
        "mma.sync.aligned.m16n8k16.row.col.f32.bf16.bf16.f32 "
        "{%0,%1,%2,%3}, {%4,%5,%6,%7}, {%8,%9}, {%0,%1,%2,%3};"
        : "+f"(c[0]), "+f"(c[1]), "+f"(c[2]), "+f"(c[3])
        : "r"(a[0]), "r"(a[1]), "r"(a[2]), "r"(a[3]), "r"(b0), "r"(b1));
}
__device__ __forceinline__ void cpa16(uint32_t s, const void* g) {
    asm volatile("cp.async.cg.shared.global [%0], [%1], 16;" :: "r"(s), "l"(g));
}
#define CP_COMMIT() asm volatile("cp.async.commit_group;" ::: "memory")
#define CP_WAIT1()  asm volatile("cp.async.wait_group 1;" ::: "memory")

// Swizzled smem tile: [rows][64 bf16] = 128B rows, 16B chunks XOR-swizzled.
__device__ __forceinline__ uint32_t lda_sw(int r, int c) {
    return (uint32_t)((r << 7) | (((c ^ (r & 7)) & 7) << 4));
}
__device__ __forceinline__ uint32_t pack_bf16(float lo_, float hi_) {
    __nv_bfloat162 t = __floats2bfloat162_rn(lo_, hi_);
    return *(uint32_t*)&t;
}
// Split v0,v1 to bf16 hi/lo and store as bf16x2 pairs.
__device__ __forceinline__ void store_hl2(__nv_bfloat16* Hp, __nv_bfloat16* Lp,
                                          size_t off, float v0, float v1) {
    __nv_bfloat16 h0 = __float2bfloat16_rn(v0);
    __nv_bfloat16 h1 = __float2bfloat16_rn(v1);
    __nv_bfloat16 l0 = __float2bfloat16_rn(v0 - __bfloat162float(h0));
    __nv_bfloat16 l1 = __float2bfloat16_rn(v1 - __bfloat162float(h1));
    *(__nv_bfloat162*)(Hp + off) = __nv_bfloat162(h0, h1);
    *(__nv_bfloat162*)(Lp + off) = __nv_bfloat162(l0, l1);
}

// ---------------------------------------------------------------------------
// Conversion kernels (only for the two raw inputs now)
// ---------------------------------------------------------------------------
__global__ void conv_x(const float* __restrict__ in) {
    size_t i = (size_t)blockIdx.x * blockDim.x + threadIdx.x;
    float4 v = ((const float4*)in)[i];
    float f[4] = {v.x, v.y, v.z, v.w};
    __nv_bfloat16 h[4], l[4];
#pragma unroll
    for (int k = 0; k < 4; k++) {
        h[k] = __float2bfloat16_rn(f[k]);
        l[k] = __float2bfloat16_rn(f[k] - __bfloat162float(h[k]));
    }
    ((__nv_bfloat162*)(g_Xhi + i * 4))[0] = __nv_bfloat162(h[0], h[1]);
    ((__nv_bfloat162*)(g_Xhi + i * 4))[1] = __nv_bfloat162(h[2], h[3]);
    ((__nv_bfloat162*)(g_Xlo + i * 4))[0] = __nv_bfloat162(l[0], l[1]);
    ((__nv_bfloat162*)(g_Xlo + i * 4))[1] = __nv_bfloat162(l[2], l[3]);
}

template<int WHICH>   // 0: w_qkv -> g_WqkvT_*, 1: w_proj -> g_WprojT_*
__global__ void transpose_split(const float* __restrict__ W, int Kdim, int Ndim) {
    __nv_bfloat16* Thi = WHICH ? g_WprojT_hi : g_WqkvT_hi;
    __nv_bfloat16* Tlo = WHICH ? g_WprojT_lo : g_WqkvT_lo;
    __shared__ float tile[32][33];
    int x = blockIdx.x * 32 + threadIdx.x;
    int y0 = blockIdx.y * 32;
#pragma unroll
    for (int j = 0; j < 32; j += 8)
        tile[threadIdx.y + j][threadIdx.x] = W[(size_t)(y0 + threadIdx.y + j) * Ndim + x];
    __syncthreads();
    int xo = y0 + threadIdx.x;
    int yo0 = blockIdx.x * 32;
#pragma unroll
    for (int j = 0; j < 32; j += 8) {
        float v = tile[threadIdx.x][threadIdx.y + j];
        __nv_bfloat16 h = __float2bfloat16_rn(v);
        __nv_bfloat16 l = __float2bfloat16_rn(v - __bfloat162float(h));
        size_t o = (size_t)(yo0 + threadIdx.y + j) * Kdim + xo;
        Thi[o] = h; Tlo[o] = l;
    }
}

// ---------------------------------------------------------------------------
// HMMA GEMM, cp.async 2-stage pipeline. 128x128 CTA tile, 8 warps (64x32
// warp tile), k-chunk 64. acc += Ahi*Bhi + Ahi*Blo + Alo*Bhi.
// CFG 0: A=g_X*, B=g_WqkvT_* -> fused epilogue writes bf16 Q (scaled) / K /
//        transposed V hi/lo. CFG 1: A=g_A2*, B=g_WprojT_* -> fp32 out + bias.
// ---------------------------------------------------------------------------
#define GEMM_STG_BYTES 65536            // Ahi,Alo,Bhi,Blo tiles [128][64]bf16
#define GEMM_SMEM (2*GEMM_STG_BYTES)    // 131072

__device__ __forceinline__ void gemm_prefetch(
    uint32_t sbase, const __nv_bfloat16* Ah, const __nv_bfloat16* Al,
    const __nv_bfloat16* Bh, const __nv_bfloat16* Bl,
    int m0, int n0, int k0, int tid) {
#pragma unroll
    for (int i = 0; i < 4; i++) {
        const int id = i * 256 + tid;
        const int r = id >> 3, ch = id & 7;
        const uint32_t so = lda_sw(r, ch);
        const size_t ga = (size_t)(m0 + r) * C_ + k0 + ch * 8;
        const size_t gb = (size_t)(n0 + r) * C_ + k0 + ch * 8;
        cpa16(sbase + so,         Ah + ga);
        cpa16(sbase + 16384 + so, Al + ga);
        cpa16(sbase + 32768 + so, Bh + gb);
        cpa16(sbase + 49152 + so, Bl + gb);
    }
}

template<int CFG>
__global__ __launch_bounds__(256) void gemm_mma(const float* __restrict__ bias,
                                               float* __restrict__ out) {
    extern __shared__ __align__(128) char gsm[];
    const __nv_bfloat16* Ah = CFG ? g_A2hi : g_Xhi;
    const __nv_bfloat16* Al = CFG ? g_A2lo : g_Xlo;
    const __nv_bfloat16* Bh = CFG ? g_WprojT_hi : g_WqkvT_hi;
    const __nv_bfloat16* Bl = CFG ? g_WprojT_lo : g_WqkvT_lo;

    const uint32_t sb = smem_to_u32(gsm);
    const int tid = threadIdx.x, lane = tid & 31, w = tid >> 5;
    const int wr = w >> 2, wc = w & 3;
    const int n0 = blockIdx.x * 128, m0 = blockIdx.y * 128;
    const int fr = lane & 15, fc = lane >> 4;

    float acc[4][4][4];
#pragma unroll
    for (int a = 0; a < 4; a++)
#pragma unroll
        for (int b = 0; b < 4; b++)
#pragma unroll
            for (int c = 0; c < 4; c++) acc[a][b][c] = 0.f;

    gemm_prefetch(sb, Ah, Al, Bh, Bl, m0, n0, 0, tid);
    CP_COMMIT();

    for (int c16 = 0; c16 < C_ / 64; c16++) {
        if (c16 + 1 < C_ / 64)
            gemm_prefetch(sb + ((c16 + 1) & 1) * GEMM_STG_BYTES,
                          Ah, Al, Bh, Bl, m0, n0, (c16 + 1) * 64, tid);
        CP_COMMIT();
        CP_WAIT1();
        __syncthreads();

        const uint32_t sAh = sb + (c16 & 1) * GEMM_STG_BYTES;
        const uint32_t sAl = sAh + 16384, sBh = sAh + 32768, sBl = sAh + 49152;
#pragma unroll
        for (int ks = 0; ks < 4; ks++) {
            uint32_t a_h[4][4], a_l[4][4];
#pragma unroll
            for (int mt = 0; mt < 4; mt++) {
                const uint32_t off = lda_sw(wr * 64 + mt * 16 + fr, 2 * ks + fc);
                ldsm4(a_h[mt], sAh + off);
                ldsm4(a_l[mt], sAl + off);
            }
#pragma unroll
            for (int nt2 = 0; nt2 < 2; nt2++) {
                uint32_t b_h[4], b_l[4];
                const uint32_t off = lda_sw(wc * 32 + nt2 * 16 + fr, 2 * ks + fc);
                ldsm4(b_h, sBh + off);
                ldsm4(b_l, sBl + off);
#pragma unroll
                for (int mt = 0; mt < 4; mt++) {
                    mma16816(acc[mt][nt2 * 2],     a_h[mt], b_h[0], b_h[2]);
                    mma16816(acc[mt][nt2 * 2 + 1], a_h[mt], b_h[1], b_h[3]);
                    mma16816(acc[mt][nt2 * 2],     a_h[mt], b_l[0], b_l[2]);
                    mma16816(acc[mt][nt2 * 2 + 1], a_h[mt], b_l[1], b_l[3]);
                    mma16816(acc[mt][nt2 * 2],     a_l[mt], b_h[0], b_h[2]);
                    mma16816(acc[mt][nt2 * 2 + 1], a_l[mt], b_h[1], b_h[3]);
                }
            }
        }
        __syncthreads();
    }

    // Epilogue
    const int grp = lane >> 2, qc = (lane & 3) * 2;
    const int which = n0 >> 10;      // CFG 0: 0=Q, 1=K, 2=V (tile fits one section)
#pragma unroll
    for (int mt = 0; mt < 4; mt++) {
        const int m1 = m0 + wr * 64 + mt * 16 + grp;
        const int m2 = m1 + 8;
        const int b1 = m1 >> 11, t1 = m1 & (T_ - 1);
        const int b2 = m2 >> 11, t2 = m2 & (T_ - 1);
#pragma unroll
        for (int nt = 0; nt < 4; nt++) {
            const int n = n0 + wc * 32 + nt * 8 + qc;
            const float bs0 = bias[n], bs1 = bias[n + 1];
            float v0 = acc[mt][nt][0] + bs0, v1 = acc[mt][nt][1] + bs1;
            float v2 = acc[mt][nt][2] + bs0, v3 = acc[mt][nt][3] + bs1;
            if (CFG == 1) {
                *(float2*)(out + (size_t)m1 * C_ + n) = make_float2(v0, v1);
                *(float2*)(out + (size_t)m2 * C_ + n) = make_float2(v2, v3);
            } else {
                const int ci = n & (C_ - 1);
                const int h = ci >> 6, d = ci & 63;
                if (which == 0) { v0 *= 0.125f; v1 *= 0.125f; v2 *= 0.125f; v3 *= 0.125f; }
                if (which < 2) {
                    __nv_bfloat16* Dh = which ? g_Khi : g_Qhi;
                    __nv_bfloat16* Dl = which ? g_Klo : g_Qlo;
                    store_hl2(Dh, Dl, (((size_t)(b1 * H_ + h)) * T_ + t1) * D_ + d, v0, v1);
                    store_hl2(Dh, Dl, (((size_t)(b2 * H_ + h)) * T_ + t2) * D_ + d, v2, v3);
                } else {
                    // transposed V: [bh][d][t]
                    const size_t oA = (((size_t)(b1 * H_ + h)) * D_ + d) * T_ + t1;
                    const size_t oB = (((size_t)(b2 * H_ + h)) * D_ + d) * T_ + t2;
                    __nv_bfloat16 h0 = __float2bfloat16_rn(v0);
                    __nv_bfloat16 h1 = __float2bfloat16_rn(v1);
                    __nv_bfloat16 h2 = __float2bfloat16_rn(v2);
                    __nv_bfloat16 h3 = __float2bfloat16_rn(v3);
                    g_Vthi[oA] = h0;      g_Vtlo[oA] = __float2bfloat16_rn(v0 - __bfloat162float(h0));
                    g_Vthi[oA + T_] = h1; g_Vtlo[oA + T_] = __float2bfloat16_rn(v1 - __bfloat162float(h1));
                    g_Vthi[oB] = h2;      g_Vtlo[oB] = __float2bfloat16_rn(v2 - __bfloat162float(h2));
                    g_Vthi[oB + T_] = h3; g_Vtlo[oB + T_] = __float2bfloat16_rn(v3 - __bfloat162float(h3));
                }
            }
        }
    }
}

// ---------------------------------------------------------------------------
// HMMA flash attention, causal, cp.async 2-stage K/V pipeline. Br=Bc=64,
// D=64, 4 warps. P hi/lo split in registers; epilogue writes g_A2 hi/lo.
// ---------------------------------------------------------------------------
#define FL_Q_BYTES 16384                 // Qhi, Qlo [64][64]bf16
#define FL_STG_BYTES 32768               // Khi,Klo,Vthi,Vtlo per stage
#define FL_SMEM (FL_Q_BYTES + 2*FL_STG_BYTES)   // 81920

__device__ __forceinline__ void fl_prefetch(uint32_t sbase, size_t bhk,
                                            size_t bhv, int kv0, int tid) {
#pragma unroll
    for (int i = 0; i < 4; i++) {
        const int id = i * 128 + tid;
        const int r = id >> 3, ch = id & 7;
        const uint32_t so = lda_sw(r, ch);
        const size_t gk = bhk + (size_t)(kv0 + r) * D_ + ch * 8;
        const size_t gv = bhv + (size_t)r * T_ + kv0 + ch * 8;
        cpa16(sbase + so,         g_Khi + gk);
        cpa16(sbase + 8192 + so,  g_Klo + gk);
        cpa16(sbase + 16384 + so, g_Vthi + gv);
        cpa16(sbase + 24576 + so, g_Vtlo + gv);
    }
}

__global__ __launch_bounds__(128) void flash_mma() {
    extern __shared__ __align__(128) char fsm[];
    const uint32_t sb = smem_to_u32(fsm);
    const uint32_t sQh = sb, sQl = sb + 8192;
    const int tid = threadIdx.x, lane = tid & 31, w = tid >> 5;
    const int bh = blockIdx.y, b = bh >> 4, h = bh & 15;
    const int qt0 = blockIdx.x * 64;
    const int fr = lane & 15, fc = lane >> 4;
    const int grp = lane >> 2, qc = (lane & 3) * 2;
    const int ntiles = blockIdx.x + 1;

    const size_t bhk = (size_t)bh * T_ * D_;
    const size_t bhv = (size_t)bh * D_ * T_;

    // Kick off first K/V stage, then load Q.
    fl_prefetch(sb + FL_Q_BYTES, bhk, bhv, 0, tid);
    CP_COMMIT();
#pragma unroll
    for (int i = 0; i < 4; i++) {
        const int id = i * 128 + tid;
        const int r = id >> 3, ch = id & 7;
        const uint32_t so = lda_sw(r, ch);
        const size_t g = bhk + (size_t)(qt0 + r) * D_ + ch * 8;
        *(uint4*)(fsm + so)        = *(const uint4*)(g_Qhi + g);
        *(uint4*)(fsm + 8192 + so) = *(const uint4*)(g_Qlo + g);
    }
    __syncthreads();

    uint32_t qh[4][4], ql[4][4];
#pragma unroll
    for (int ks = 0; ks < 4; ks++) {
        const uint32_t off = lda_sw(w * 16 + fr, 2 * ks + fc);
        ldsm4(qh[ks], sQh + off);
        ldsm4(ql[ks], sQl + off);
    }

    float o[8][4];
#pragma unroll
    for (int d = 0; d < 8; d++)
#pragma unroll
        for (int r = 0; r < 4; r++) o[d][r] = 0.f;
    float mA = -1e30f, mB = -1e30f, lA = 0.f, lB = 0.f;

    const int rowA = qt0 + w * 16 + grp;
    const int rowB = rowA + 8;

    for (int it = 0; it < ntiles; it++) {
        if (it + 1 < ntiles)
            fl_prefetch(sb + FL_Q_BYTES + ((it + 1) & 1) * FL_STG_BYTES,
                        bhk, bhv, (it + 1) * 64, tid);
        CP_COMMIT();
        CP_WAIT1();
        __syncthreads();

        const uint32_t sKh = sb + FL_Q_BYTES + (it & 1) * FL_STG_BYTES;
        const uint32_t sKl = sKh + 8192, sVh = sKh + 16384, sVl = sKh + 24576;
        const int kv0 = it * 64;

        // S = Q K^T (3 terms, scale pre-folded into Q)
        float s[8][4];
#pragma unroll
        for (int nt = 0; nt < 8; nt++)
#pragma unroll
            for (int r = 0; r < 4; r++) s[nt][r] = 0.f;

#pragma unroll
        for (int ks = 0; ks < 4; ks++) {
#pragma unroll
            for (int nt2 = 0; nt2 < 4; nt2++) {
                uint32_t bhr[4], blr[4];
                const uint32_t off = lda_sw(nt2 * 16 + fr, 2 * ks + fc);
                ldsm4(bhr, sKh + off);
                ldsm4(blr, sKl + off);
                mma16816(s[nt2 * 2],     qh[ks], bhr[0], bhr[2]);
                mma16816(s[nt2 * 2 + 1], qh[ks], bhr[1], bhr[3]);
                mma16816(s[nt2 * 2],     qh[ks], blr[0], blr[2]);
                mma16816(s[nt2 * 2 + 1], qh[ks], blr[1], blr[3]);
                mma16816(s[nt2 * 2],     ql[ks], bhr[0], bhr[2]);
                mma16816(s[nt2 * 2 + 1], ql[ks], bhr[1], bhr[3]);
            }
        }

        if (kv0 == qt0) {   // diagonal tile: causal mask
#pragma unroll
            for (int nt = 0; nt < 8; nt++) {
                const int cb = kv0 + nt * 8 + qc;
                if (cb > rowA)     s[nt][0] = -1e30f;
                if (cb + 1 > rowA) s[nt][1] = -1e30f;
                if (cb > rowB)     s[nt][2] = -1e30f;
                if (cb + 1 > rowB) s[nt][3] = -1e30f;
            }
        }

        // Online softmax
        float mxA = -1e30f, mxB = -1e30f;
#pragma unroll
        for (int nt = 0; nt < 8; nt++) {
            mxA = fmaxf(mxA, fmaxf(s[nt][0], s[nt][1]));
            mxB = fmaxf(mxB, fmaxf(s[nt][2], s[nt][3]));
        }
        mxA = fmaxf(mxA, __shfl_xor_sync(0xffffffffu, mxA, 1));
        mxA = fmaxf(mxA, __shfl_xor_sync(0xffffffffu, mxA, 2));
        mxB = fmaxf(mxB, __shfl_xor_sync(0xffffffffu, mxB, 1));
        mxB = fmaxf(mxB, __shfl_xor_sync(0xffffffffu, mxB, 2));
        const float nmA = fmaxf(mA, mxA), nmB = fmaxf(mB, mxB);
        const float aA = __expf(mA - nmA), aB = __expf(mB - nmB);

        float p[8][4];
        float sumA = 0.f, sumB = 0.f;
#pragma unroll
        for (int nt = 0; nt < 8; nt++) {
            p[nt][0] = __expf(s[nt][0] - nmA);
            p[nt][1] = __expf(s[nt][1] - nmA);
            p[nt][2] = __expf(s[nt][2] - nmB);
            p[nt][3] = __expf(s[nt][3] - nmB);
            sumA += p[nt][0] + p[nt][1];
            sumB += p[nt][2] + p[nt][3];
        }
        sumA += __shfl_xor_sync(0xffffffffu, sumA, 1);
        sumA += __shfl_xor_sync(0xffffffffu, sumA, 2);
        sumB += __shfl_xor_sync(0xffffffffu, sumB, 1);
        sumB += __shfl_xor_sync(0xffffffffu, sumB, 2);
        lA = lA * aA + sumA;
        lB = lB * aB + sumB;
        mA = nmA; mB = nmB;
#pragma unroll
        for (int d = 0; d < 8; d++) {
            o[d][0] *= aA; o[d][1] *= aA;
            o[d][2] *= aB; o[d][3] *= aB;
        }

        // O += P * Vt (P hi/lo split in registers)
#pragma unroll
        for (int ks = 0; ks < 4; ks++) {
            float f0 = p[2 * ks][0], f1 = p[2 * ks][1];
            float f2 = p[2 * ks][2], f3 = p[2 * ks][3];
            float f4 = p[2 * ks + 1][0], f5 = p[2 * ks + 1][1];
            float f6 = p[2 * ks + 1][2], f7 = p[2 * ks + 1][3];
            float h0 = __bfloat162float(__float2bfloat16_rn(f0));
            float h1 = __bfloat162float(__float2bfloat16_rn(f1));
            float h2 = __bfloat162float(__float2bfloat16_rn(f2));
            float h3 = __bfloat162float(__float2bfloat16_rn(f3));
            float h4 = __bfloat162float(__float2bfloat16_rn(f4));
            float h5 = __bfloat162float(__float2bfloat16_rn(f5));
            float h6 = __bfloat162float(__float2bfloat16_rn(f6));
            float h7 = __bfloat162float(__float2bfloat16_rn(f7));
            uint32_t pa_h[4], pa_l[4];
            pa_h[0] = pack_bf16(h0, h1); pa_h[1] = pack_bf16(h2, h3);
            pa_h[2] = pack_bf16(h4, h5); pa_h[3] = pack_bf16(h6, h7);
            pa_l[0] = pack_bf16(f0 - h0, f1 - h1);
            pa_l[1] = pack_bf16(f2 - h2, f3 - h3);
            pa_l[2] = pack_bf16(f4 - h4, f5 - h5);
            pa_l[3] = pack_bf16(f6 - h6, f7 - h7);
#pragma unroll
            for (int dt2 = 0; dt2 < 4; dt2++) {
                uint32_t vh4[4], vl4[4];
                const uint32_t off = lda_sw(dt2 * 16 + fr, 2 * ks + fc);
                ldsm4(vh4, sVh + off);
                ldsm4(vl4, sVl + off);
                mma16816(o[dt2 * 2],     pa_h, vh4[0], vh4[2]);
                mma16816(o[dt2 * 2 + 1], pa_h, vh4[1], vh4[3]);
                mma16816(o[dt2 * 2],     pa_h, vl4[0], vl4[2]);
                mma16816(o[dt2 * 2 + 1], pa_h, vl4[1], vl4[3]);
                mma16816(o[dt2 * 2],     pa_l, vh4[0], vh4[2]);
                mma16816(o[dt2 * 2 + 1], pa_l, vh4[1], vh4[3]);
            }
        }
        __syncthreads();
    }

    // Fused epilogue: normalize and write bf16 hi/lo directly to g_A2*
    const float invA = 1.0f / lA, invB = 1.0f / lB;
    const size_t baseA = ((size_t)(b * T_ + rowA)) * C_ + h * D_;
    const size_t baseB = ((size_t)(b * T_ + rowB)) * C_ + h * D_;
#pragma unroll
    for (int dt = 0; dt < 8; dt++) {
        const int d = dt * 8 + qc;
        store_hl2(g_A2hi, g_A2lo, baseA + d, o[dt][0] * invA, o[dt][1] * invA);
        store_hl2(g_A2hi, g_A2lo, baseB + d, o[dt][2] * invB, o[dt][3] * invB);
    }
}

// ---------------------------------------------------------------------------
extern "C" void kernel_launch(void* const* d_in, const int* in_sizes, int n_in,
                              void* d_out, int out_size) {
    const float* x      = (const float*)d_in[0];
    const float* w_qkv  = (const float*)d_in[1];
    const float* b_qkv  = (const float*)d_in[2];
    const float* w_proj = (const float*)d_in[3];
    const float* b_proj = (const float*)d_in[4];
    float* out = (float*)d_out;

    cudaFuncSetAttribute(gemm_mma<0>, cudaFuncAttributeMaxDynamicSharedMemorySize, GEMM_SMEM);
    cudaFuncSetAttribute(gemm_mma<1>, cudaFuncAttributeMaxDynamicSharedMemorySize, GEMM_SMEM);
    cudaFuncSetAttribute(flash_mma,   cudaFuncAttributeMaxDynamicSharedMemorySize, FL_SMEM);

    // 0) input conversions
    conv_x<<<(M_ * C_ / 4) / 256, 256>>>(x);
    transpose_split<0><<<dim3(N3_ / 32, C_ / 32), dim3(32, 8)>>>(w_qkv, C_, N3_);
    transpose_split<1><<<dim3(C_ / 32, C_ / 32), dim3(32, 8)>>>(w_proj, C_, C_);

    // 1) QKV GEMM (pipelined HMMA) -> fused bf16 Q/K/Vt epilogue
    gemm_mma<0><<<dim3(N3_ / 128, M_ / 128), 256, GEMM_SMEM>>>(b_qkv, nullptr);

    // 2) Causal flash attention (pipelined HMMA) -> g_A2 hi/lo
    flash_mma<<<dim3(T_ / 64, BH_), 128, FL_SMEM>>>();

    // 3) Output projection (pipelined HMMA) -> fp32 out
    gemm_mma<1><<<dim3(C_ / 128, M_ / 128), 256, GEMM_SMEM>>>(b_proj, out);
}